// round 15
// baseline (speedup 1.0000x reference)
#include <cuda_runtime.h>

#define Bn   32
#define Nn   1024
#define MLc  3
#define HIDn 100
#define ODIM 147
#define CK   13
#define WP   16            // padded weight-row stride
#define WPAD (CK * WP)     // 208

// interior tile: 64x64, block = 256 threads (8 warps), 4 blocks/SM
#define TSZ  64
#define IXS  78    // TSZ + 14
#define IXP  79
#define IRS  76    // TSZ + 12
#define IRP  76
#define QR   19    // rows per parity-4 array (76/4)

// dynamic smem layout (float offsets)
#define OFF_SX   0
#define OFF_R0   6164                 // 78*79 = 6162, +2 pad -> 16B aligned
#define RARR     (QR * IRP)           // 1444 floats per parity array
#define OFF_SW   (OFF_R0 + 4 * RARR)  // 11940
#define SMEM_FLOATS (OFF_SW + WPAD)   // 12148
#define SMEM_BYTES  (SMEM_FLOATS * 4) // 48592

// frame-path offsets (same buffer; max 8449 < 12148)
#define FOFF_SX  0
#define FOFF_SR  2416
#define FOFF_ST  4520
#define FOFF_W1  8140
#define FOFF_W2  8290
#define FOFF_KA  8440

#define NTX  16
#define NINT (NTX * NTX)     // 256 interior blocks

__device__ float g_w1[Bn][ODIM];
__device__ float g_w2[Bn][ODIM];
__device__ float g_W13p[Bn][WPAD];

// ---------------------------------------------------------------------------
// Kernel 0: both MLPs (ILP-10 layer 2) + composite 13x13 (padded). 768 thr.
// ---------------------------------------------------------------------------
__global__ __launch_bounds__(768)
void mlp_kernel(const float* __restrict__ kA,
                const float* __restrict__ w1a, const float* __restrict__ b1a,
                const float* __restrict__ w2a, const float* __restrict__ b2a,
                const float* __restrict__ w1b, const float* __restrict__ b1b,
                const float* __restrict__ w2b, const float* __restrict__ b2b) {
    const int b = blockIdx.x;
    const int t = threadIdx.x;
    const int path = t / 384;
    const int s = t - path * 384;
    __shared__ float skA[9];
    __shared__ float h[2][HIDn];
    __shared__ float part[2][ODIM][2];
    __shared__ float sh1[ODIM];
    __shared__ float sh2[ODIM];

    if (t < 9) skA[t] = kA[b * 9 + t];
    __syncthreads();

    const float* W1 = path ? w1b : w1a;
    const float* B1 = path ? b1b : b1a;
    const float* W2 = path ? w2b : w2a;
    const float* B2 = path ? b2b : b2a;

    if (s < HIDn) {
        float acc = B1[s];
#pragma unroll
        for (int k = 0; k < 9; k++) acc += skA[k] * W1[k * HIDn + s];
        h[path][s] = fmaxf(acc, 0.f);
    }
    __syncthreads();

    {
        const int o = s >> 1, half = s & 1;
        if (o < ODIM) {
            const int k0 = half * 50;
            float a[10];
#pragma unroll
            for (int j = 0; j < 10; j++) a[j] = 0.f;
#pragma unroll
            for (int kk = 0; kk < 5; kk++)
#pragma unroll
                for (int j = 0; j < 10; j++)
                    a[j] += h[path][k0 + kk * 10 + j] * W2[(k0 + kk * 10 + j) * ODIM + o];
            float acc = (((a[0] + a[1]) + (a[2] + a[3])) + ((a[4] + a[5]) + (a[6] + a[7]))) + (a[8] + a[9]);
            if (half == 0) acc += B2[o];
            part[path][o][half] = acc;
        }
    }
    __syncthreads();

    if (t < 2 * ODIM) {
        int pp = t / ODIM, o = t - pp * ODIM;
        float acc = part[pp][o][0] + part[pp][o][1];
        if (pp) { sh2[o] = acc; g_w2[b][o] = acc; }
        else    { sh1[o] = acc; g_w1[b][o] = acc; }
    }
    __syncthreads();

    if (t < WPAD) {
        int u = t >> 4, v = t & 15;
        float acc = 0.f;
        if (v < CK) {
            int i0 = max(0, u - 6), i1 = min(6, u);
            int j0 = max(0, v - 6), j1 = min(6, v);
            for (int m = 0; m < MLc; m++)
                for (int i = i0; i <= i1; i++)
                    for (int j = j0; j <= j1; j++)
                        acc += sh2[m * 49 + i * 7 + j] * sh1[m * 49 + (u - i) * 7 + (v - j)];
        }
        g_W13p[b][t] = acc;
    }
}

// apply one 13-tap weight row (padded base wp) to acc[4] using rv[0..15]
__device__ __forceinline__ void apply_row4(const float* __restrict__ wp,
                                           const float rv[16], float acc[4]) {
    const float4* wq = reinterpret_cast<const float4*>(wp);
    float4 wa = wq[0];
#pragma unroll
    for (int k = 0; k < 4; k++) acc[k] = fmaf(wa.x, rv[0 + k], acc[k]);
#pragma unroll
    for (int k = 0; k < 4; k++) acc[k] = fmaf(wa.y, rv[1 + k], acc[k]);
#pragma unroll
    for (int k = 0; k < 4; k++) acc[k] = fmaf(wa.z, rv[2 + k], acc[k]);
#pragma unroll
    for (int k = 0; k < 4; k++) acc[k] = fmaf(wa.w, rv[3 + k], acc[k]);
    float4 wb = wq[1];
#pragma unroll
    for (int k = 0; k < 4; k++) acc[k] = fmaf(wb.x, rv[4 + k], acc[k]);
#pragma unroll
    for (int k = 0; k < 4; k++) acc[k] = fmaf(wb.y, rv[5 + k], acc[k]);
#pragma unroll
    for (int k = 0; k < 4; k++) acc[k] = fmaf(wb.z, rv[6 + k], acc[k]);
#pragma unroll
    for (int k = 0; k < 4; k++) acc[k] = fmaf(wb.w, rv[7 + k], acc[k]);
    float4 wc = wq[2];
#pragma unroll
    for (int k = 0; k < 4; k++) acc[k] = fmaf(wc.x, rv[8 + k], acc[k]);
#pragma unroll
    for (int k = 0; k < 4; k++) acc[k] = fmaf(wc.y, rv[9 + k], acc[k]);
#pragma unroll
    for (int k = 0; k < 4; k++) acc[k] = fmaf(wc.z, rv[10 + k], acc[k]);
#pragma unroll
    for (int k = 0; k < 4; k++) acc[k] = fmaf(wc.w, rv[11 + k], acc[k]);
    float w12 = wp[12];
#pragma unroll
    for (int k = 0; k < 4; k++) acc[k] = fmaf(w12, rv[12 + k], acc[k]);
}

__device__ __forceinline__ void load_rv16(const float* __restrict__ p, float rv[16]) {
    const float4* q = reinterpret_cast<const float4*>(p);
#pragma unroll
    for (int m = 0; m < 4; m++) {
        float4 t = q[m];
        rv[4 * m + 0] = t.x; rv[4 * m + 1] = t.y;
        rv[4 * m + 2] = t.z; rv[4 * m + 3] = t.w;
    }
}

// ---------------------------------------------------------------------------
// Fused kernel. grid (288, Bn), block 256, dynamic smem 48.6 KB, 4 blocks/SM.
// blockIdx.x < 256 -> interior 64x64 tile; else frame segment.
// ---------------------------------------------------------------------------
__global__ __launch_bounds__(256, 4)
void fused_kernel(const float* __restrict__ x, const float* __restrict__ f,
                  const float* __restrict__ kA, float* __restrict__ out) {
    extern __shared__ __align__(16) float smem[];
    const int b   = blockIdx.y;
    const int tid = threadIdx.x;
    const int lane = tid & 31;
    const int wid  = tid >> 5;          // 0..7

    const float* xb = x + (size_t)b * Nn * Nn;
    const float* fb = f + (size_t)b * Nn * Nn;
    float*       ob = out + (size_t)b * Nn * Nn;

    if (blockIdx.x < NINT) {
        // ================= interior path =================
        const int bx = blockIdx.x & (NTX - 1), by = blockIdx.x >> 4;
        const int ty0 = by * TSZ, tx0 = bx * TSZ;
        const bool edge = (bx == 0) | (bx == NTX - 1) | (by == 0) | (by == NTX - 1);

        float* sx = smem + OFF_SX;
        float* sW = smem + OFF_SW;
        float* sR0 = smem + OFF_R0;              // parity-4 arrays
        float* sR1 = sR0 + RARR;
        float* sR2 = sR1 + RARR;
        float* sR3 = sR2 + RARR;

        if (tid < WPAD) sW[tid] = g_W13p[b][tid];
        __shared__ float skA[9];
        if (tid < 9) skA[tid] = kA[b * 9 + tid];

        if (!edge) {
            // Stage A: x region 78x78 (origin -7)
#pragma unroll 1
            for (int u = wid; u < IXS; u += 8) {
                const float* gp = &xb[(ty0 - 7 + u) * Nn + tx0 - 7];
                float* sp = &sx[u * IXP];
#pragma unroll
                for (int v = lane; v < IXS; v += 32) sp[v] = gp[v];
            }
            __syncthreads();
            // Stage B: r = f - corr3(x,kA), 76x76, parity-4 split
            float k0 = skA[0], k1 = skA[1], k2 = skA[2],
                  k3 = skA[3], k4 = skA[4], k5 = skA[5],
                  k6 = skA[6], k7 = skA[7], k8 = skA[8];
            // u = wid + 8t -> u&3 = wid&3 fixed per warp
            float* dstBase = (wid & 2) ? ((wid & 1) ? sR3 : sR2)
                                       : ((wid & 1) ? sR1 : sR0);
#pragma unroll 1
            for (int u = wid; u < IRS; u += 8) {
                const float* gp = &fb[(ty0 - 6 + u) * Nn + tx0 - 6];
                const float* xp = &sx[(u + 1) * IXP + 1];
                float* sp = &dstBase[(u >> 2) * IRP];
#pragma unroll
                for (int v = lane; v < IRS; v += 32) {
                    float acc = gp[v];
                    acc -= k0 * xp[-IXP + v - 1];
                    acc -= k1 * xp[-IXP + v];
                    acc -= k2 * xp[-IXP + v + 1];
                    acc -= k3 * xp[v - 1];
                    acc -= k4 * xp[v];
                    acc -= k5 * xp[v + 1];
                    acc -= k6 * xp[IXP + v - 1];
                    acc -= k7 * xp[IXP + v];
                    acc -= k8 * xp[IXP + v + 1];
                    sp[v] = acc;
                }
            }
        } else {
#pragma unroll 1
            for (int u = wid; u < IXS; u += 8) {
                int gy = ty0 - 7 + u;
                bool rok = (gy >= 0 && gy < Nn);
                float* sp = &sx[u * IXP];
#pragma unroll
                for (int v = lane; v < IXS; v += 32) {
                    int gx = tx0 - 7 + v;
                    sp[v] = (rok && gx >= 0 && gx < Nn) ? xb[gy * Nn + gx] : 0.f;
                }
            }
            __syncthreads();
            float k0 = skA[0], k1 = skA[1], k2 = skA[2],
                  k3 = skA[3], k4 = skA[4], k5 = skA[5],
                  k6 = skA[6], k7 = skA[7], k8 = skA[8];
            float* dstBase = (wid & 2) ? ((wid & 1) ? sR3 : sR2)
                                       : ((wid & 1) ? sR1 : sR0);
#pragma unroll 1
            for (int u = wid; u < IRS; u += 8) {
                int gy = ty0 - 6 + u;
                bool rok = (gy >= 0 && gy < Nn);
                float* sp = &dstBase[(u >> 2) * IRP];
                const float* xp = &sx[(u + 1) * IXP + 1];
#pragma unroll
                for (int v = lane; v < IRS; v += 32) {
                    int gx = tx0 - 6 + v;
                    float val = 0.f;
                    if (rok && gx >= 0 && gx < Nn) {
                        float acc = fb[gy * Nn + gx];
                        acc -= k0 * xp[-IXP + v - 1];
                        acc -= k1 * xp[-IXP + v];
                        acc -= k2 * xp[-IXP + v + 1];
                        acc -= k3 * xp[v - 1];
                        acc -= k4 * xp[v];
                        acc -= k5 * xp[v + 1];
                        acc -= k6 * xp[IXP + v - 1];
                        acc -= k7 * xp[IXP + v];
                        acc -= k8 * xp[IXP + v + 1];
                        val = acc;
                    }
                    sp[v] = val;
                }
            }
        }
        __syncthreads();

        // Stage C: quad rows x 4-px strips.
        // pr = (wid<<1)+(lane>>4) in 0..15; v0 = (lane&15)*4.
        // Output rows ty0+4pr..+3; r rows 4pr+u (u=0..15):
        //   array = u&3 (compile-time under unroll), row = pr + (u>>2).
        const int pr = (wid << 1) + (lane >> 4);
        const int v0 = (lane & 15) << 2;
        float acc[4][4];
#pragma unroll
        for (int d = 0; d < 4; d++)
#pragma unroll
            for (int k = 0; k < 4; k++) acc[d][k] = 0.f;

        const float* base0 = &sR0[pr * IRP + v0];
        const float* base1 = &sR1[pr * IRP + v0];
        const float* base2 = &sR2[pr * IRP + v0];
        const float* base3 = &sR3[pr * IRP + v0];
        float rv[16];

#pragma unroll
        for (int u = 0; u < 16; u++) {
            const float* p;
            switch (u & 3) {                 // folds at compile time
                case 0: p = base0 + (u >> 2) * IRP; break;
                case 1: p = base1 + (u >> 2) * IRP; break;
                case 2: p = base2 + (u >> 2) * IRP; break;
                default: p = base3 + (u >> 2) * IRP; break;
            }
            load_rv16(p, rv);
            const int dy0 = (u > 12) ? (u - 12) : 0;
            const int dy1 = (u < 3) ? u : 3;
#pragma unroll
            for (int dy = 0; dy < 4; dy++) {
                if (dy >= dy0 && dy <= dy1)
                    apply_row4(&sW[(u - dy) * WP], rv, acc[dy]);
            }
        }

        // direct store: 4 rows, lanes 0-15 contiguous 256B segments
        const int gy0 = ty0 + 4 * pr;
        const int gx0 = tx0 + v0;
        if (!edge) {
#pragma unroll
            for (int d = 0; d < 4; d++) {
                const float4 xv = *reinterpret_cast<const float4*>(&xb[(gy0 + d) * Nn + gx0]);
                float4 q;
                q.x = acc[d][0] + xv.x; q.y = acc[d][1] + xv.y;
                q.z = acc[d][2] + xv.z; q.w = acc[d][3] + xv.w;
                *reinterpret_cast<float4*>(&ob[(gy0 + d) * Nn + gx0]) = q;
            }
        } else {
#pragma unroll
            for (int d = 0; d < 4; d++) {
                int gy = gy0 + d;
                if (gy < 3 || gy >= Nn - 3) continue;
#pragma unroll
                for (int k = 0; k < 4; k++) {
                    int gx = gx0 + k;
                    if (gx >= 3 && gx < Nn - 3)
                        ob[gy * Nn + gx] = xb[gy * Nn + gx] + acc[d][k];
                }
            }
        }
        return;
    }

    // ================= frame path (exact two-stage, 3-px border) ============
    const int seg = blockIdx.x - NINT;
    int oy0, ox0, OH, OW;
    if (seg < 8)       { oy0 = 0;    OH = 3; ox0 = seg * 128;        OW = 128; }
    else if (seg < 16) { oy0 = 1021; OH = 3; ox0 = (seg - 8) * 128;  OW = 128; }
    else if (seg < 24) { ox0 = 0;    OW = 3; oy0 = 3 + (seg - 16) * 128; OH = min(128, 1021 - oy0); }
    else               { ox0 = 1021; OW = 3; oy0 = 3 + (seg - 24) * 128; OH = min(128, 1021 - oy0); }
    const int TH = OH + 6,  TW = OW + 6;
    const int RH = OH + 12, RW = OW + 12;
    const int XH = OH + 14, XW = OW + 14;

    float* sx = smem + FOFF_SX;
    float* sr = smem + FOFF_SR;
    float* st = smem + FOFF_ST;
    float* sw1 = smem + FOFF_W1;
    float* sw2 = smem + FOFF_W2;
    float* skA = smem + FOFF_KA;

    if (tid < ODIM) { sw1[tid] = g_w1[b][tid]; sw2[tid] = g_w2[b][tid]; }
    if (tid < 9) skA[tid] = kA[b * 9 + tid];
    __syncthreads();

    for (int p = tid; p < XH * XW; p += 256) {
        int i = p / XW, j = p % XW;
        int gy = oy0 - 7 + i, gx = ox0 - 7 + j;
        sx[p] = (gy >= 0 && gy < Nn && gx >= 0 && gx < Nn) ? xb[gy * Nn + gx] : 0.f;
    }
    __syncthreads();

    for (int p = tid; p < RH * RW; p += 256) {
        int i = p / RW, j = p % RW;
        int gy = oy0 - 6 + i, gx = ox0 - 6 + j;
        float v = 0.f;
        if (gy >= 0 && gy < Nn && gx >= 0 && gx < Nn) {
            v = fb[gy * Nn + gx];
#pragma unroll
            for (int a = 0; a < 3; a++)
#pragma unroll
                for (int c = 0; c < 3; c++)
                    v -= skA[a * 3 + c] * sx[(i + a) * XW + (j + c)];
        }
        sr[p] = v;
    }
    __syncthreads();

    const int TA = TH * TW;
    for (int p = tid; p < 3 * TA; p += 256) {
        int m = p / TA, q = p - m * TA;
        int i = q / TW, j = q % TW;
        int gy = oy0 - 3 + i, gx = ox0 - 3 + j;
        float v = 0.f;
        if (gy >= 0 && gy < Nn && gx >= 0 && gx < Nn) {
#pragma unroll
            for (int a = 0; a < 7; a++)
#pragma unroll
                for (int c = 0; c < 7; c++)
                    v += sw1[m * 49 + a * 7 + c] * sr[(i + a) * RW + (j + c)];
        }
        st[m * TA + q] = v;
    }
    __syncthreads();

    for (int p = tid; p < OH * OW; p += 256) {
        int y = p / OW, xc = p % OW;
        float v = sx[(y + 7) * XW + (xc + 7)];
#pragma unroll
        for (int m = 0; m < MLc; m++)
#pragma unroll
            for (int a = 0; a < 7; a++)
#pragma unroll
                for (int c = 0; c < 7; c++)
                    v += sw2[m * 49 + a * 7 + c] * st[m * TA + (y + a) * TW + (xc + c)];
        ob[(oy0 + y) * Nn + (ox0 + xc)] = v;
    }
}

// ---------------------------------------------------------------------------
extern "C" void kernel_launch(void* const* d_in, const int* in_sizes, int n_in,
                              void* d_out, int out_size) {
    const float* x      = (const float*)d_in[0];
    const float* f      = (const float*)d_in[1];
    const float* kA     = (const float*)d_in[2];
    const float* fc1_w1 = (const float*)d_in[3];
    const float* fc1_b1 = (const float*)d_in[4];
    const float* fc1_w2 = (const float*)d_in[5];
    const float* fc1_b2 = (const float*)d_in[6];
    const float* fc2_w1 = (const float*)d_in[7];
    const float* fc2_b1 = (const float*)d_in[8];
    const float* fc2_w2 = (const float*)d_in[9];
    const float* fc2_b2 = (const float*)d_in[10];
    float* out = (float*)d_out;

    cudaFuncSetAttribute(fused_kernel,
                         cudaFuncAttributeMaxDynamicSharedMemorySize, SMEM_BYTES);

    mlp_kernel<<<Bn, 768>>>(kA, fc1_w1, fc1_b1, fc1_w2, fc1_b2,
                            fc2_w1, fc2_b1, fc2_w2, fc2_b2);

    dim3 g(NINT + 32, Bn);
    fused_kernel<<<g, 256, SMEM_BYTES>>>(x, f, kA, out);
}

// round 16
// speedup vs baseline: 1.0979x; 1.0979x over previous
#include <cuda_runtime.h>

#define Bn   32
#define Nn   1024
#define MLc  3
#define HIDn 100
#define ODIM 147
#define CK   13
#define WP   16            // padded weight-row stride
#define WPAD (CK * WP)     // 208

// interior tile: 64x64, block = 512 threads (16 warps), 3 blocks/SM
#define TSZ  64
#define IXS  78    // TSZ + 14
#define IXP  79
#define IRS  76    // TSZ + 12
#define IRP  76
#define HR   38    // IRS/2 rows per parity array

// dynamic smem layout (float offsets)
#define OFF_SX   0
#define OFF_SE   6164                 // 78*79 = 6162, +2 pad -> 16B aligned
#define OFF_SO   (OFF_SE + HR * IRP)  // 9052
#define OFF_SW   (OFF_SO + HR * IRP)  // 11940
#define SMEM_FLOATS (OFF_SW + WPAD)   // 12148
#define SMEM_BYTES  (SMEM_FLOATS * 4) // 48592

// frame-path offsets (same buffer; max 8449 < 12148)
#define FOFF_SX  0
#define FOFF_SR  2416
#define FOFF_ST  4520
#define FOFF_W1  8140
#define FOFF_W2  8290
#define FOFF_KA  8440

#define NTX  16
#define NINT (NTX * NTX)     // 256 interior blocks

__device__ float g_w1[Bn][ODIM];
__device__ float g_w2[Bn][ODIM];
__device__ float g_W13p[Bn][WPAD];

// ---------------------------------------------------------------------------
// Kernel 0: both MLPs (ILP-10 layer 2) + composite 13x13 (padded). 768 thr.
// ---------------------------------------------------------------------------
__global__ __launch_bounds__(768)
void mlp_kernel(const float* __restrict__ kA,
                const float* __restrict__ w1a, const float* __restrict__ b1a,
                const float* __restrict__ w2a, const float* __restrict__ b2a,
                const float* __restrict__ w1b, const float* __restrict__ b1b,
                const float* __restrict__ w2b, const float* __restrict__ b2b) {
    const int b = blockIdx.x;
    const int t = threadIdx.x;
    const int path = t / 384;
    const int s = t - path * 384;
    __shared__ float skA[9];
    __shared__ float h[2][HIDn];
    __shared__ float part[2][ODIM][2];
    __shared__ float sh1[ODIM];
    __shared__ float sh2[ODIM];

    if (t < 9) skA[t] = kA[b * 9 + t];
    __syncthreads();

    const float* W1 = path ? w1b : w1a;
    const float* B1 = path ? b1b : b1a;
    const float* W2 = path ? w2b : w2a;
    const float* B2 = path ? b2b : b2a;

    if (s < HIDn) {
        float acc = B1[s];
#pragma unroll
        for (int k = 0; k < 9; k++) acc += skA[k] * W1[k * HIDn + s];
        h[path][s] = fmaxf(acc, 0.f);
    }
    __syncthreads();

    {
        const int o = s >> 1, half = s & 1;
        if (o < ODIM) {
            const int k0 = half * 50;
            float a[10];
#pragma unroll
            for (int j = 0; j < 10; j++) a[j] = 0.f;
#pragma unroll
            for (int kk = 0; kk < 5; kk++)
#pragma unroll
                for (int j = 0; j < 10; j++)
                    a[j] += h[path][k0 + kk * 10 + j] * W2[(k0 + kk * 10 + j) * ODIM + o];
            float acc = (((a[0] + a[1]) + (a[2] + a[3])) + ((a[4] + a[5]) + (a[6] + a[7]))) + (a[8] + a[9]);
            if (half == 0) acc += B2[o];
            part[path][o][half] = acc;
        }
    }
    __syncthreads();

    if (t < 2 * ODIM) {
        int pp = t / ODIM, o = t - pp * ODIM;
        float acc = part[pp][o][0] + part[pp][o][1];
        if (pp) { sh2[o] = acc; g_w2[b][o] = acc; }
        else    { sh1[o] = acc; g_w1[b][o] = acc; }
    }
    __syncthreads();

    if (t < WPAD) {
        int u = t >> 4, v = t & 15;
        float acc = 0.f;
        if (v < CK) {
            int i0 = max(0, u - 6), i1 = min(6, u);
            int j0 = max(0, v - 6), j1 = min(6, v);
            for (int m = 0; m < MLc; m++)
                for (int i = i0; i <= i1; i++)
                    for (int j = j0; j <= j1; j++)
                        acc += sh2[m * 49 + i * 7 + j] * sh1[m * 49 + (u - i) * 7 + (v - j)];
        }
        g_W13p[b][t] = acc;
    }
}

// apply one 13-tap weight row (padded base wp) to acc[4] using rv[0..15]
__device__ __forceinline__ void apply_row4(const float* __restrict__ wp,
                                           const float rv[16], float acc[4]) {
    const float4* wq = reinterpret_cast<const float4*>(wp);
    float4 wa = wq[0];
#pragma unroll
    for (int k = 0; k < 4; k++) acc[k] = fmaf(wa.x, rv[0 + k], acc[k]);
#pragma unroll
    for (int k = 0; k < 4; k++) acc[k] = fmaf(wa.y, rv[1 + k], acc[k]);
#pragma unroll
    for (int k = 0; k < 4; k++) acc[k] = fmaf(wa.z, rv[2 + k], acc[k]);
#pragma unroll
    for (int k = 0; k < 4; k++) acc[k] = fmaf(wa.w, rv[3 + k], acc[k]);
    float4 wb = wq[1];
#pragma unroll
    for (int k = 0; k < 4; k++) acc[k] = fmaf(wb.x, rv[4 + k], acc[k]);
#pragma unroll
    for (int k = 0; k < 4; k++) acc[k] = fmaf(wb.y, rv[5 + k], acc[k]);
#pragma unroll
    for (int k = 0; k < 4; k++) acc[k] = fmaf(wb.z, rv[6 + k], acc[k]);
#pragma unroll
    for (int k = 0; k < 4; k++) acc[k] = fmaf(wb.w, rv[7 + k], acc[k]);
    float4 wc = wq[2];
#pragma unroll
    for (int k = 0; k < 4; k++) acc[k] = fmaf(wc.x, rv[8 + k], acc[k]);
#pragma unroll
    for (int k = 0; k < 4; k++) acc[k] = fmaf(wc.y, rv[9 + k], acc[k]);
#pragma unroll
    for (int k = 0; k < 4; k++) acc[k] = fmaf(wc.z, rv[10 + k], acc[k]);
#pragma unroll
    for (int k = 0; k < 4; k++) acc[k] = fmaf(wc.w, rv[11 + k], acc[k]);
    float w12 = wp[12];
#pragma unroll
    for (int k = 0; k < 4; k++) acc[k] = fmaf(w12, rv[12 + k], acc[k]);
}

__device__ __forceinline__ void load_rv16(const float* __restrict__ p, float rv[16]) {
    const float4* q = reinterpret_cast<const float4*>(p);
#pragma unroll
    for (int m = 0; m < 4; m++) {
        float4 t = q[m];
        rv[4 * m + 0] = t.x; rv[4 * m + 1] = t.y;
        rv[4 * m + 2] = t.z; rv[4 * m + 3] = t.w;
    }
}

// ---------------------------------------------------------------------------
// Fused kernel. grid (288, Bn), block 512, dynamic smem 48.6 KB, 3 blocks/SM.
// blockIdx.x < 256 -> interior 64x64 tile; else frame segment.
// ---------------------------------------------------------------------------
__global__ __launch_bounds__(512, 3)
void fused_kernel(const float* __restrict__ x, const float* __restrict__ f,
                  const float* __restrict__ kA, float* __restrict__ out) {
    extern __shared__ __align__(16) float smem[];
    const int b   = blockIdx.y;
    const int tid = threadIdx.x;
    const int lane = tid & 31;
    const int wid  = tid >> 5;          // 0..15

    const float* xb = x + (size_t)b * Nn * Nn;
    const float* fb = f + (size_t)b * Nn * Nn;
    float*       ob = out + (size_t)b * Nn * Nn;

    if (blockIdx.x < NINT) {
        // ================= interior path =================
        const int bx = blockIdx.x & (NTX - 1), by = blockIdx.x >> 4;
        const int ty0 = by * TSZ, tx0 = bx * TSZ;
        const bool edge = (bx == 0) | (bx == NTX - 1) | (by == 0) | (by == NTX - 1);

        float* sx = smem + OFF_SX;
        float* sE = smem + OFF_SE;
        float* sO = smem + OFF_SO;
        float* sW = smem + OFF_SW;

        if (tid < WPAD) sW[tid] = g_W13p[b][tid];
        __shared__ float skA[9];
        if (tid < 9) skA[tid] = kA[b * 9 + tid];
        __syncthreads();                // sW/skA visible

        float k0 = skA[0], k1 = skA[1], k2 = skA[2],
              k3 = skA[3], k4 = skA[4], k5 = skA[5],
              k6 = skA[6], k7 = skA[7], k8 = skA[8];

        if (!edge) {
            // Stage B only: r rows (u2*2, u2*2+1) per thread-iter, x via LDG.
            // u = 2*(wid + 16t): u&2 warp-uniform? u = 2wid + 32t -> (u>>1)&1 =
            // wid&1 fixed; sE gets even rows, sO odd rows, both index u2.
#pragma unroll 1
            for (int u2 = wid; u2 < HR; u2 += 16) {
                const int gy = ty0 - 6 + 2 * u2;     // even r row
                float* e = &sE[u2 * IRP];
                float* o = &sO[u2 * IRP];
                const float* xrow = &xb[(size_t)(gy - 1) * Nn + tx0 - 6];
#pragma unroll
                for (int v = lane; v < IRS; v += 32) {
                    const float* xp = xrow + v;
                    // rows gy-1..gy+2, cols -1..+1 relative
                    float a0 = __ldg(xp - 1),       a1 = __ldg(xp),       a2 = __ldg(xp + 1);
                    float b0 = __ldg(xp + Nn - 1),  b1 = __ldg(xp + Nn),  b2 = __ldg(xp + Nn + 1);
                    float c0 = __ldg(xp + 2*Nn - 1),c1 = __ldg(xp + 2*Nn),c2 = __ldg(xp + 2*Nn + 1);
                    float d0 = __ldg(xp + 3*Nn - 1),d1 = __ldg(xp + 3*Nn),d2 = __ldg(xp + 3*Nn + 1);
                    float r0 = fb[(size_t)gy * Nn + tx0 - 6 + v];
                    r0 -= k0 * a0; r0 -= k1 * a1; r0 -= k2 * a2;
                    r0 -= k3 * b0; r0 -= k4 * b1; r0 -= k5 * b2;
                    r0 -= k6 * c0; r0 -= k7 * c1; r0 -= k8 * c2;
                    float r1 = fb[(size_t)(gy + 1) * Nn + tx0 - 6 + v];
                    r1 -= k0 * b0; r1 -= k1 * b1; r1 -= k2 * b2;
                    r1 -= k3 * c0; r1 -= k4 * c1; r1 -= k5 * c2;
                    r1 -= k6 * d0; r1 -= k7 * d1; r1 -= k8 * d2;
                    e[v] = r0;
                    o[v] = r1;
                }
            }
        } else {
            // edge: stage A (zero-padded smem) then 1-row stage B
#pragma unroll 1
            for (int u = wid; u < IXS; u += 16) {
                int gy = ty0 - 7 + u;
                bool rok = (gy >= 0 && gy < Nn);
                float* sp = &sx[u * IXP];
#pragma unroll
                for (int v = lane; v < IXS; v += 32) {
                    int gx = tx0 - 7 + v;
                    sp[v] = (rok && gx >= 0 && gx < Nn) ? xb[gy * Nn + gx] : 0.f;
                }
            }
            __syncthreads();
            float* dstBase = (wid & 1) ? sO : sE;
#pragma unroll 1
            for (int u = wid; u < IRS; u += 16) {
                int gy = ty0 - 6 + u;
                bool rok = (gy >= 0 && gy < Nn);
                float* sp = &dstBase[(u >> 1) * IRP];
                const float* xp = &sx[(u + 1) * IXP + 1];
#pragma unroll
                for (int v = lane; v < IRS; v += 32) {
                    int gx = tx0 - 6 + v;
                    float val = 0.f;
                    if (rok && gx >= 0 && gx < Nn) {
                        float acc = fb[gy * Nn + gx];
                        acc -= k0 * xp[-IXP + v - 1];
                        acc -= k1 * xp[-IXP + v];
                        acc -= k2 * xp[-IXP + v + 1];
                        acc -= k3 * xp[v - 1];
                        acc -= k4 * xp[v];
                        acc -= k5 * xp[v + 1];
                        acc -= k6 * xp[IXP + v - 1];
                        acc -= k7 * xp[IXP + v];
                        acc -= k8 * xp[IXP + v + 1];
                        val = acc;
                    }
                    sp[v] = val;
                }
            }
        }
        __syncthreads();

        // Stage C: paired rows, 4-wide strips (R14 engine, unchanged).
        // pr = (wid<<1)+(lane>>4) in 0..31; v0 = (lane&15)*4.
        const int pr = (wid << 1) + (lane >> 4);
        const int v0 = (lane & 15) << 2;
        float acc0[4], acc1[4];
#pragma unroll
        for (int k = 0; k < 4; k++) { acc0[k] = 0.f; acc1[k] = 0.f; }
        const float* pe = &sE[pr * IRP + v0];
        const float* po = &sO[pr * IRP + v0];
        float rv[16];

        load_rv16(pe, rv);
        apply_row4(&sW[0], rv, acc0);
#pragma unroll 1
        for (int t = 0; t < 6; t++) {
            load_rv16(po + t * IRP, rv);
            apply_row4(&sW[(2 * t + 1) * WP], rv, acc0);
            apply_row4(&sW[(2 * t) * WP], rv, acc1);
            load_rv16(pe + (t + 1) * IRP, rv);
            apply_row4(&sW[(2 * t + 2) * WP], rv, acc0);
            apply_row4(&sW[(2 * t + 1) * WP], rv, acc1);
        }
        load_rv16(po + 6 * IRP, rv);
        apply_row4(&sW[12 * WP], rv, acc1);

        // direct store: coalesced (lanes 0-15 = contiguous 256B row segment)
        const int gy0 = ty0 + 2 * pr;
        const int gx0 = tx0 + v0;
        if (!edge) {
            const float4 xv0 = *reinterpret_cast<const float4*>(&xb[gy0 * Nn + gx0]);
            const float4 xv1 = *reinterpret_cast<const float4*>(&xb[(gy0 + 1) * Nn + gx0]);
            float4 q0, q1;
            q0.x = acc0[0] + xv0.x; q0.y = acc0[1] + xv0.y;
            q0.z = acc0[2] + xv0.z; q0.w = acc0[3] + xv0.w;
            q1.x = acc1[0] + xv1.x; q1.y = acc1[1] + xv1.y;
            q1.z = acc1[2] + xv1.z; q1.w = acc1[3] + xv1.w;
            *reinterpret_cast<float4*>(&ob[gy0 * Nn + gx0]) = q0;
            *reinterpret_cast<float4*>(&ob[(gy0 + 1) * Nn + gx0]) = q1;
        } else {
#pragma unroll
            for (int rr = 0; rr < 2; rr++) {
                int gy = gy0 + rr;
                if (gy < 3 || gy >= Nn - 3) continue;
#pragma unroll
                for (int k = 0; k < 4; k++) {
                    int gx = gx0 + k;
                    if (gx >= 3 && gx < Nn - 3) {
                        float av = rr ? acc1[k] : acc0[k];
                        ob[gy * Nn + gx] = xb[gy * Nn + gx] + av;
                    }
                }
            }
        }
        return;
    }

    // ================= frame path (exact two-stage, 3-px border) ============
    const int seg = blockIdx.x - NINT;
    int oy0, ox0, OH, OW;
    if (seg < 8)       { oy0 = 0;    OH = 3; ox0 = seg * 128;        OW = 128; }
    else if (seg < 16) { oy0 = 1021; OH = 3; ox0 = (seg - 8) * 128;  OW = 128; }
    else if (seg < 24) { ox0 = 0;    OW = 3; oy0 = 3 + (seg - 16) * 128; OH = min(128, 1021 - oy0); }
    else               { ox0 = 1021; OW = 3; oy0 = 3 + (seg - 24) * 128; OH = min(128, 1021 - oy0); }
    const int TH = OH + 6,  TW = OW + 6;
    const int RH = OH + 12, RW = OW + 12;
    const int XH = OH + 14, XW = OW + 14;

    float* sx = smem + FOFF_SX;
    float* sr = smem + FOFF_SR;
    float* st = smem + FOFF_ST;
    float* sw1 = smem + FOFF_W1;
    float* sw2 = smem + FOFF_W2;
    float* skA = smem + FOFF_KA;

    if (tid < ODIM) { sw1[tid] = g_w1[b][tid]; sw2[tid] = g_w2[b][tid]; }
    if (tid < 9) skA[tid] = kA[b * 9 + tid];
    __syncthreads();

    for (int p = tid; p < XH * XW; p += 512) {
        int i = p / XW, j = p % XW;
        int gy = oy0 - 7 + i, gx = ox0 - 7 + j;
        sx[p] = (gy >= 0 && gy < Nn && gx >= 0 && gx < Nn) ? xb[gy * Nn + gx] : 0.f;
    }
    __syncthreads();

    for (int p = tid; p < RH * RW; p += 512) {
        int i = p / RW, j = p % RW;
        int gy = oy0 - 6 + i, gx = ox0 - 6 + j;
        float v = 0.f;
        if (gy >= 0 && gy < Nn && gx >= 0 && gx < Nn) {
            v = fb[gy * Nn + gx];
#pragma unroll
            for (int a = 0; a < 3; a++)
#pragma unroll
                for (int c = 0; c < 3; c++)
                    v -= skA[a * 3 + c] * sx[(i + a) * XW + (j + c)];
        }
        sr[p] = v;
    }
    __syncthreads();

    const int TA = TH * TW;
    for (int p = tid; p < 3 * TA; p += 512) {
        int m = p / TA, q = p - m * TA;
        int i = q / TW, j = q % TW;
        int gy = oy0 - 3 + i, gx = ox0 - 3 + j;
        float v = 0.f;
        if (gy >= 0 && gy < Nn && gx >= 0 && gx < Nn) {
#pragma unroll
            for (int a = 0; a < 7; a++)
#pragma unroll
                for (int c = 0; c < 7; c++)
                    v += sw1[m * 49 + a * 7 + c] * sr[(i + a) * RW + (j + c)];
        }
        st[m * TA + q] = v;
    }
    __syncthreads();

    for (int p = tid; p < OH * OW; p += 512) {
        int y = p / OW, xc = p % OW;
        float v = sx[(y + 7) * XW + (xc + 7)];
#pragma unroll
        for (int m = 0; m < MLc; m++)
#pragma unroll
            for (int a = 0; a < 7; a++)
#pragma unroll
                for (int c = 0; c < 7; c++)
                    v += sw2[m * 49 + a * 7 + c] * st[m * TA + (y + a) * TW + (xc + c)];
        ob[(oy0 + y) * Nn + (ox0 + xc)] = v;
    }
}

// ---------------------------------------------------------------------------
extern "C" void kernel_launch(void* const* d_in, const int* in_sizes, int n_in,
                              void* d_out, int out_size) {
    const float* x      = (const float*)d_in[0];
    const float* f      = (const float*)d_in[1];
    const float* kA     = (const float*)d_in[2];
    const float* fc1_w1 = (const float*)d_in[3];
    const float* fc1_b1 = (const float*)d_in[4];
    const float* fc1_w2 = (const float*)d_in[5];
    const float* fc1_b2 = (const float*)d_in[6];
    const float* fc2_w1 = (const float*)d_in[7];
    const float* fc2_b1 = (const float*)d_in[8];
    const float* fc2_w2 = (const float*)d_in[9];
    const float* fc2_b2 = (const float*)d_in[10];
    float* out = (float*)d_out;

    cudaFuncSetAttribute(fused_kernel,
                         cudaFuncAttributeMaxDynamicSharedMemorySize, SMEM_BYTES);

    mlp_kernel<<<Bn, 768>>>(kA, fc1_w1, fc1_b1, fc1_w2, fc1_b2,
                            fc2_w1, fc2_b1, fc2_w2, fc2_b2);

    dim3 g(NINT + 32, Bn);
    fused_kernel<<<g, 512, SMEM_BYTES>>>(x, f, kA, out);
}